// round 4
// baseline (speedup 1.0000x reference)
#include <cuda_runtime.h>
#include <cstdint>

// ---------------------------------------------------------------------------
// Problem: B=16, S=512, F=512, H=8, D=512.
// ---------------------------------------------------------------------------
__device__ float g_Q[16 * 512 * 4096];
__device__ float g_K[16 * 512 * 4096];
__device__ float g_V[16 * 512 * 4096];
__device__ float g_VT[128 * 512 * 512];
__device__ float g_P[128 * 512 * 512];
__device__ float g_WT[3 * 4096 * 512];

// ===========================================================================
// Helpers
// ===========================================================================
__device__ __forceinline__ uint32_t smem_u32(const void* p) {
    uint32_t a;
    asm("{ .reg .u64 t; cvta.to.shared.u64 t, %1; cvt.u32.u64 %0, t; }"
        : "=r"(a) : "l"(p));
    return a;
}

__device__ __forceinline__ void split_tf32(float x, uint32_t& h, uint32_t& l) {
    asm("cvt.rna.tf32.f32 %0, %1;" : "=r"(h) : "f"(x));
    float lf = x - __uint_as_float(h);
    asm("cvt.rna.tf32.f32 %0, %1;" : "=r"(l) : "f"(lf));
}

__device__ __forceinline__ void mma8(float* c, const uint32_t* a, const uint32_t* b) {
    asm volatile(
        "mma.sync.aligned.m16n8k8.row.col.f32.tf32.tf32.f32 "
        "{%0,%1,%2,%3}, {%4,%5,%6,%7}, {%8,%9}, {%0,%1,%2,%3};"
        : "+f"(c[0]), "+f"(c[1]), "+f"(c[2]), "+f"(c[3])
        : "r"(a[0]), "r"(a[1]), "r"(a[2]), "r"(a[3]), "r"(b[0]), "r"(b[1]));
}

__device__ __forceinline__ void lds128(uint32_t* r, uint32_t a) {
    asm volatile("ld.shared.v4.b32 {%0,%1,%2,%3}, [%4];"
                 : "=r"(r[0]), "=r"(r[1]), "=r"(r[2]), "=r"(r[3]) : "r"(a));
}
__device__ __forceinline__ void lds64(uint32_t* r, uint32_t a) {
    asm volatile("ld.shared.v2.b32 {%0,%1}, [%2];"
                 : "=r"(r[0]), "=r"(r[1]) : "r"(a));
}
__device__ __forceinline__ void sts128(uint32_t a, uint32_t x, uint32_t y,
                                       uint32_t z, uint32_t w) {
    asm volatile("st.shared.v4.b32 [%0], {%1,%2,%3,%4};"
                 :: "r"(a), "r"(x), "r"(y), "r"(z), "r"(w) : "memory");
}
__device__ __forceinline__ void sts64(uint32_t a, uint32_t x, uint32_t y) {
    asm volatile("st.shared.v2.b32 [%0], {%1,%2};"
                 :: "r"(a), "r"(x), "r"(y) : "memory");
}

#define MBAR_INIT(addr, cnt) \
    asm volatile("mbarrier.init.shared.b64 [%0], %1;" :: "r"(addr), "r"(cnt) : "memory")
#define MBAR_ARRIVE(addr) \
    asm volatile("mbarrier.arrive.shared.b64 _, [%0];" :: "r"(addr) : "memory")

#define MBAR_WAIT(addr, parity) do {                                              \
    uint32_t _m = (addr); uint32_t _p = (parity); uint32_t _done;                 \
    asm volatile(                                                                 \
        "{\n\t.reg .pred p;\n\t"                                                  \
        "mbarrier.try_wait.parity.acquire.cta.shared::cta.b64 p, [%1], %2;\n\t"   \
        "selp.b32 %0, 1, 0, p;\n\t}"                                              \
        : "=r"(_done) : "r"(_m), "r"(_p) : "memory");                             \
    if (!_done) {                                                                 \
        asm volatile(                                                             \
            "{\n\t.reg .pred P1;\n\t"                                             \
            "WL_%=:\n\t"                                                          \
            "mbarrier.try_wait.parity.acquire.cta.shared::cta.b64 P1, [%0], %1, 0x989680;\n\t" \
            "@P1 bra.uni WD_%=;\n\t"                                              \
            "bra.uni WL_%=;\n\t"                                                  \
            "WD_%=:\n\t}"                                                         \
            :: "r"(_m), "r"(_p) : "memory");                                      \
    }                                                                             \
} while (0)

// ===========================================================================
// Warp-specialized NT GEMM, 3xTF32 emulation.
//   C[128x256] = A[M,512] @ B[N,512]^T  (row-major, K contiguous)
// 384 threads: warps 0-7 consumers (2x4 grid, 64x64 warp tile),
//              warps 8-11 producers (LDG -> split -> fragment-packed SMEM).
// Ring: 4 stages x KB=16. Stage layout (bytes):
//   [0,8192)      A_hi quads: (((ks*8+rb)*8+g)*4+tg)*16  (quad = frag a0..a3)
//   [8192,16384)  A_lo quads
//   [16384,32768) B_hi pairs: ((ks*256+o)*4+tg)*8        (pair = frag b0,b1)
//   [32768,49152) B_lo pairs
// ===========================================================================
#define KB        16
#define NKB       32
#define NSTG      4
#define STAGE     49152
#define GEMM_SMEM (NSTG * STAGE)   // 196608

__device__ __forceinline__ void gemm_nt(const float* __restrict__ A, int lda,
                                        const float* __restrict__ B, int ldb,
                                        float* __restrict__ C, int ldc)
{
    extern __shared__ char smc[];
    __shared__ uint64_t s_bar[8];            // full[0..3], empty[4..7]
    const uint32_t sa  = smem_u32(smc);
    const uint32_t bar = smem_u32(s_bar);

    const int tid = threadIdx.x;

    if (tid == 0) {
#pragma unroll
        for (int s = 0; s < 4; ++s) MBAR_INIT(bar + s * 8, 128);       // full
#pragma unroll
        for (int s = 0; s < 4; ++s) MBAR_INIT(bar + 32 + s * 8, 256);  // empty
    }
    __syncthreads();

    if (tid >= 256) {
        // =================== PRODUCER (warps 8-11) =========================
        const int pt = tid - 256;              // 0..127
        const int ag  = pt & 7;
        const int arb = (pt >> 3) & 7;
        const int aks = pt >> 6;
        const float* Ab = A + (size_t)(blockIdx.y * 128) * lda;
        const float* Bb = B + (size_t)(blockIdx.x * 256) * ldb;
        const float* ar0 = Ab + (size_t)(arb * 16 + ag) * lda + aks * 8;
        const float* ar1 = ar0 + (size_t)8 * lda;
        const uint32_t aoff = (uint32_t)(((aks * 8 + arb) * 8 + ag) * 4) * 16;

        int ph = 1;
        for (int st = 0; st < NKB; ++st) {
            const int buf = st & 3;
            MBAR_WAIT(bar + 32 + buf * 8, ph);
            if (buf == 3) ph ^= 1;
            const uint32_t sbase = sa + buf * STAGE;
            const int kc = st * KB;

            // ---- A: 1 (row-pair, k-half) task per thread ----
            {
                const float4 v00 = *reinterpret_cast<const float4*>(ar0 + kc);
                const float4 v01 = *reinterpret_cast<const float4*>(ar0 + kc + 4);
                const float4 v10 = *reinterpret_cast<const float4*>(ar1 + kc);
                const float4 v11 = *reinterpret_cast<const float4*>(ar1 + kc + 4);
                const float q[4][4] = {
                    {v00.x, v10.x, v01.x, v11.x},
                    {v00.y, v10.y, v01.y, v11.y},
                    {v00.z, v10.z, v01.z, v11.z},
                    {v00.w, v10.w, v01.w, v11.w}};
#pragma unroll
                for (int tg = 0; tg < 4; ++tg) {
                    uint32_t h0, l0, h1, l1, h2, l2, h3, l3;
                    split_tf32(q[tg][0], h0, l0);
                    split_tf32(q[tg][1], h1, l1);
                    split_tf32(q[tg][2], h2, l2);
                    split_tf32(q[tg][3], h3, l3);
                    sts128(sbase + aoff + tg * 16, h0, h1, h2, h3);
                    sts128(sbase + 8192 + aoff + tg * 16, l0, l1, l2, l3);
                }
            }
            // ---- B: 4 (row, k-half) tasks per thread ----
#pragma unroll
            for (int itr = 0; itr < 4; ++itr) {
                const int task = pt + itr * 128;
                const int o = task & 255;
                const int bks = task >> 8;
                const float* pb = Bb + (size_t)o * ldb + kc + bks * 8;
                const float4 w0 = *reinterpret_cast<const float4*>(pb);
                const float4 w1 = *reinterpret_cast<const float4*>(pb + 4);
                const uint32_t boff = sbase + 16384 + (uint32_t)((bks * 256 + o) * 4) * 8;
                const float p0[4] = {w0.x, w0.y, w0.z, w0.w};
                const float p1[4] = {w1.x, w1.y, w1.z, w1.w};
#pragma unroll
                for (int tg = 0; tg < 4; ++tg) {
                    uint32_t h0, l0, h1, l1;
                    split_tf32(p0[tg], h0, l0);
                    split_tf32(p1[tg], h1, l1);
                    sts64(boff + tg * 8, h0, h1);
                    sts64(boff + 16384 + tg * 8, l0, l1);
                }
            }
            MBAR_ARRIVE(bar + buf * 8);
        }
    } else {
        // =================== CONSUMER (warps 0-7) ==========================
        const int wid = tid >> 5;
        const int lid = tid & 31;
        const int wr  = wid >> 2;        // 0..1 (M)
        const int wc  = wid & 3;         // 0..3 (N)
        const int g   = lid >> 2;
        const int tg  = lid & 3;

        float acc[4][8][4];
#pragma unroll
        for (int mt = 0; mt < 4; ++mt)
#pragma unroll
            for (int nt = 0; nt < 8; ++nt)
#pragma unroll
                for (int i = 0; i < 4; ++i) acc[mt][nt][i] = 0.0f;

        const uint32_t aBase = (uint32_t)(((wr * 4) * 8 + g) * 4 + tg) * 16;
        const uint32_t bBase = (uint32_t)((wc * 64 + g) * 4 + tg) * 8;

        int ph = 0;
        for (int kb = 0; kb < NKB; ++kb) {
            const int buf = kb & 3;
            MBAR_WAIT(bar + buf * 8, ph);
            if (buf == 3) ph ^= 1;
            const uint32_t sbase = sa + buf * STAGE;

#pragma unroll
            for (int ks = 0; ks < 2; ++ks) {
                const uint32_t aAdr = sbase + aBase + ks * 4096;
                const uint32_t bAdr = sbase + 16384 + bBase + ks * 8192;
                uint32_t aR[4][4], bR[8][2];

                // pass 1: a_hi * b_hi
#pragma unroll
                for (int mt = 0; mt < 4; ++mt) lds128(aR[mt], aAdr + mt * 512);
#pragma unroll
                for (int nt = 0; nt < 8; ++nt) lds64(bR[nt], bAdr + nt * 256);
#pragma unroll
                for (int mt = 0; mt < 4; ++mt)
#pragma unroll
                    for (int nt = 0; nt < 8; ++nt) mma8(acc[mt][nt], aR[mt], bR[nt]);

                // pass 2: a_hi * b_lo
#pragma unroll
                for (int nt = 0; nt < 8; ++nt) lds64(bR[nt], bAdr + 16384 + nt * 256);
#pragma unroll
                for (int mt = 0; mt < 4; ++mt)
#pragma unroll
                    for (int nt = 0; nt < 8; ++nt) mma8(acc[mt][nt], aR[mt], bR[nt]);

                // pass 3: a_lo * b_hi
#pragma unroll
                for (int mt = 0; mt < 4; ++mt) lds128(aR[mt], aAdr + 8192 + mt * 512);
#pragma unroll
                for (int nt = 0; nt < 8; ++nt) lds64(bR[nt], bAdr + nt * 256);
#pragma unroll
                for (int mt = 0; mt < 4; ++mt)
#pragma unroll
                    for (int nt = 0; nt < 8; ++nt) mma8(acc[mt][nt], aR[mt], bR[nt]);
            }
            MBAR_ARRIVE(bar + 32 + buf * 8);
        }

        // ---- epilogue ----
        const int rbase = blockIdx.y * 128 + wr * 64 + g;
        const int cbase = blockIdx.x * 256 + wc * 64 + tg * 2;
#pragma unroll
        for (int mt = 0; mt < 4; ++mt) {
#pragma unroll
            for (int nt = 0; nt < 8; ++nt) {
                const int r = rbase + mt * 16;
                const int c = cbase + nt * 8;
                *reinterpret_cast<float2*>(&C[(size_t)r * ldc + c]) =
                    make_float2(acc[mt][nt][0], acc[mt][nt][1]);
                *reinterpret_cast<float2*>(&C[(size_t)(r + 8) * ldc + c]) =
                    make_float2(acc[mt][nt][2], acc[mt][nt][3]);
            }
        }
    }
}

// ===========================================================================
// GEMM wrappers
// ===========================================================================
__global__ void __launch_bounds__(384, 1)
proj_mm(const float* __restrict__ x)
{
    const int z = blockIdx.z;
    const float* B = g_WT + (size_t)z * 4096 * 512;
    float* C = (z == 0) ? g_Q : (z == 1) ? g_K : g_V;
    gemm_nt(x, 512, B, 512, C, 4096);
}

__global__ void __launch_bounds__(384, 1)
qk_mm()
{
    const int z = blockIdx.z;
    const int h = z >> 4, b = z & 15;
    const float* A = g_Q + (size_t)b * 512 * 4096 + h * 512;
    const float* B = g_K + (size_t)b * 512 * 4096 + h * 512;
    float* C = g_P + (size_t)z * 512 * 512;
    gemm_nt(A, 4096, B, 4096, C, 512);
}

__global__ void __launch_bounds__(384, 1)
pv_mm(float* __restrict__ out)
{
    const int z = blockIdx.z;
    const int h = z >> 4, b = z & 15;
    const float* A = g_P + (size_t)z * 512 * 512;
    const float* B = g_VT + (size_t)z * 512 * 512;
    float* C = out + (size_t)b * 512 * 4096 + h * 512;
    gemm_nt(A, 512, B, 512, C, 4096);
}

// ===========================================================================
// Transposes
// ===========================================================================
__global__ void wt_kernel(const float* __restrict__ wq,
                          const float* __restrict__ wk,
                          const float* __restrict__ wv)
{
    __shared__ float t[32][33];
    const int z = blockIdx.z;
    const float* W = (z == 0) ? wq : (z == 1) ? wk : wv;
    float* WT = g_WT + (size_t)z * 4096 * 512;
    const int n0 = blockIdx.x * 32, k0 = blockIdx.y * 32;
    const int tx = threadIdx.x, ty = threadIdx.y;
#pragma unroll
    for (int i = 0; i < 4; ++i)
        t[ty + i * 8][tx] = W[(size_t)(k0 + ty + i * 8) * 4096 + n0 + tx];
    __syncthreads();
#pragma unroll
    for (int i = 0; i < 4; ++i)
        WT[(size_t)(n0 + ty + i * 8) * 512 + k0 + tx] = t[tx][ty + i * 8];
}

__global__ void vt_kernel()
{
    __shared__ float t[32][33];
    const int z = blockIdx.z;
    const int h = z >> 4, b = z & 15;
    const int j0 = blockIdx.x * 32, d0 = blockIdx.y * 32;
    const int tx = threadIdx.x, ty = threadIdx.y;
#pragma unroll
    for (int i = 0; i < 4; ++i)
        t[ty + i * 8][tx] = g_V[(size_t)(b * 512 + j0 + ty + i * 8) * 4096 + h * 512 + d0 + tx];
    __syncthreads();
    float* VT = g_VT + (size_t)z * 512 * 512;
#pragma unroll
    for (int i = 0; i < 4; ++i)
        VT[(size_t)(d0 + ty + i * 8) * 512 + j0 + tx] = t[tx][ty + i * 8];
}

// ===========================================================================
// Softmax over rows of g_P (length 512), one block per row
// ===========================================================================
__global__ void softmax_kernel()
{
    float* p = g_P + (size_t)blockIdx.x * 512;
    const int t = threadIdx.x;

    float2 v = reinterpret_cast<float2*>(p)[t];
    __shared__ float red[8];

    float m = fmaxf(v.x, v.y);
#pragma unroll
    for (int o = 16; o > 0; o >>= 1) m = fmaxf(m, __shfl_xor_sync(0xFFFFFFFFu, m, o));
    if ((t & 31) == 0) red[t >> 5] = m;
    __syncthreads();
    m = red[0];
#pragma unroll
    for (int i = 1; i < 8; i++) m = fmaxf(m, red[i]);
    __syncthreads();

    const float e0 = __expf(v.x - m);
    const float e1 = __expf(v.y - m);

    float s = e0 + e1;
#pragma unroll
    for (int o = 16; o > 0; o >>= 1) s += __shfl_xor_sync(0xFFFFFFFFu, s, o);
    if ((t & 31) == 0) red[t >> 5] = s;
    __syncthreads();
    s = red[0];
#pragma unroll
    for (int i = 1; i < 8; i++) s += red[i];

    const float inv = 1.0f / s;
    reinterpret_cast<float2*>(p)[t] = make_float2(e0 * inv, e1 * inv);
}

// ===========================================================================
// Launch
// ===========================================================================
extern "C" void kernel_launch(void* const* d_in, const int* in_sizes, int n_in,
                              void* d_out, int out_size)
{
    const float* x  = (const float*)d_in[0];
    const float* wq = (const float*)d_in[1];
    const float* wk = (const float*)d_in[2];
    const float* wv = (const float*)d_in[3];
    float* out = (float*)d_out;

    cudaFuncSetAttribute(proj_mm, cudaFuncAttributeMaxDynamicSharedMemorySize, GEMM_SMEM);
    cudaFuncSetAttribute(qk_mm,   cudaFuncAttributeMaxDynamicSharedMemorySize, GEMM_SMEM);
    cudaFuncSetAttribute(pv_mm,   cudaFuncAttributeMaxDynamicSharedMemorySize, GEMM_SMEM);

    wt_kernel<<<dim3(128, 16, 3), dim3(32, 8)>>>(wq, wk, wv);
    proj_mm<<<dim3(16, 64, 3), 384, GEMM_SMEM>>>(x);
    vt_kernel<<<dim3(16, 16, 128), dim3(32, 8)>>>();
    qk_mm<<<dim3(2, 4, 128), 384, GEMM_SMEM>>>();
    softmax_kernel<<<65536, 256>>>();
    pv_mm<<<dim3(2, 4, 128), 384, GEMM_SMEM>>>(out);
}

// round 5
// speedup vs baseline: 2.4944x; 2.4944x over previous
#include <cuda_runtime.h>
#include <cuda_bf16.h>
#include <cstdint>

// ---------------------------------------------------------------------------
// Problem: B=16, S=512, F=512, H=8, D=512.
// All GEMM operands are pre-split into bf16 hi/lo planes (x = hi + lo).
// ---------------------------------------------------------------------------
__device__ float g_V[16 * 512 * 4096];      // V projection fp32 (pre-transpose)
__device__ float g_P[128 * 512 * 512];      // scores fp32 (softmax input)

__device__ __nv_bfloat16 g_xh[8192 * 512],       g_xl[8192 * 512];
__device__ __nv_bfloat16 g_WTh[3 * 4096 * 512],  g_WTl[3 * 4096 * 512];
__device__ __nv_bfloat16 g_Qh[8192 * 4096],      g_Ql[8192 * 4096];
__device__ __nv_bfloat16 g_Kh[8192 * 4096],      g_Kl[8192 * 4096];
__device__ __nv_bfloat16 g_VTh[128 * 512 * 512], g_VTl[128 * 512 * 512];
__device__ __nv_bfloat16 g_Ph[128 * 512 * 512],  g_Pl[128 * 512 * 512];

// ===========================================================================
// Helpers
// ===========================================================================
__device__ __forceinline__ uint32_t smem_u32(const void* p) {
    uint32_t a;
    asm("{ .reg .u64 t; cvta.to.shared.u64 t, %1; cvt.u32.u64 %0, t; }"
        : "=r"(a) : "l"(p));
    return a;
}

__device__ __forceinline__ void cp16(uint32_t dst, const void* src) {
    asm volatile("cp.async.cg.shared.global [%0], [%1], 16;"
                 :: "r"(dst), "l"(src) : "memory");
}
#define CP_COMMIT() asm volatile("cp.async.commit_group;" ::: "memory")
#define CP_WAIT1()  asm volatile("cp.async.wait_group 1;" ::: "memory")

// pack two fp32 into bf16x2 hi-plane word + lo-plane word (rn rounding)
__device__ __forceinline__ void pack2(float x0, float x1, uint32_t& h, uint32_t& l) {
    asm("cvt.rn.bf16x2.f32 %0, %1, %2;" : "=r"(h) : "f"(x1), "f"(x0));
    float f0 = __uint_as_float(h << 16);
    float f1 = __uint_as_float(h & 0xFFFF0000u);
    float l0 = x0 - f0, l1 = x1 - f1;
    asm("cvt.rn.bf16x2.f32 %0, %1, %2;" : "=r"(l) : "f"(l1), "f"(l0));
}

// D += A * B : m16n8k16 bf16, row.col, fp32 accumulate
__device__ __forceinline__ void mma16(float* c, const uint32_t* a, const uint32_t* b) {
    asm volatile(
        "mma.sync.aligned.m16n8k16.row.col.f32.bf16.bf16.f32 "
        "{%0,%1,%2,%3}, {%4,%5,%6,%7}, {%8,%9}, {%0,%1,%2,%3};"
        : "+f"(c[0]), "+f"(c[1]), "+f"(c[2]), "+f"(c[3])
        : "r"(a[0]), "r"(a[1]), "r"(a[2]), "r"(a[3]), "r"(b[0]), "r"(b[1]));
}

__device__ __forceinline__ uint32_t lds32(uint32_t a) {
    uint32_t r;
    asm volatile("ld.shared.b32 %0, [%1];" : "=r"(r) : "r"(a));
    return r;
}

// ===========================================================================
// NT GEMM on bf16 hi/lo planes (3-term emulation of fp32).
//   C[128x256] = A[M,512] @ B[N,512]^T   (planes row-major, K contiguous)
// 256 threads = 8 warps (2M x 4N), warp tile 64x64, m16n8k16 frags.
// SMEM stage (KB=32 k-elems): rows padded to 80B (64B data + 16B pad):
//   A_hi [0,10240) A_lo [10240,20480) B_hi [20480,40960) B_lo [40960,61440)
// 3-stage cp.async ring.
// ===========================================================================
#define KB        32
#define NKB       16
#define NSTG      3
#define STR       80
#define STAGE     61440
#define GEMM_SMEM (NSTG * STAGE)   // 184320

// EPI: 0 -> write fp32 C;  1 -> write bf16 hi/lo planes Ch/Cl
template <int EPI>
__device__ __forceinline__ void gemm_nt_bf16(
    const __nv_bfloat16* __restrict__ Ah, const __nv_bfloat16* __restrict__ Al, int lda,
    const __nv_bfloat16* __restrict__ Bh, const __nv_bfloat16* __restrict__ Bl, int ldb,
    float* __restrict__ C, __nv_bfloat16* __restrict__ Ch,
    __nv_bfloat16* __restrict__ Cl, int ldc)
{
    extern __shared__ char smc[];
    const uint32_t sa = smem_u32(smc);

    const int tid = threadIdx.x;
    const int wid = tid >> 5;
    const int lid = tid & 31;
    const int wr  = wid >> 2;        // 0..1 (M)
    const int wc  = wid & 3;         // 0..3 (N)
    const int g   = lid >> 2;        // 0..7
    const int tg  = lid & 3;         // 0..3

    const __nv_bfloat16* Abh = Ah + (size_t)(blockIdx.y * 128) * lda;
    const __nv_bfloat16* Abl = Al + (size_t)(blockIdx.y * 128) * lda;
    const __nv_bfloat16* Bbh = Bh + (size_t)(blockIdx.x * 256) * ldb;
    const __nv_bfloat16* Bbl = Bl + (size_t)(blockIdx.x * 256) * ldb;

    auto load_stage = [&](int buf, int kb) {
        const uint32_t dbase = sa + buf * STAGE;
        const int kc = kb * KB;
#pragma unroll
        for (int i = 0; i < 4; ++i) {               // A: 1024 chunks
            const int t = tid + (i << 8);
            const int pl = t >> 9, row = (t >> 2) & 127, c = t & 3;
            const __nv_bfloat16* src = (pl ? Abl : Abh) + (size_t)row * lda + kc + c * 8;
            cp16(dbase + pl * 10240 + row * STR + c * 16, src);
        }
#pragma unroll
        for (int i = 0; i < 8; ++i) {               // B: 2048 chunks
            const int t = tid + (i << 8);
            const int pl = t >> 10, row = (t >> 2) & 255, c = t & 3;
            const __nv_bfloat16* src = (pl ? Bbl : Bbh) + (size_t)row * ldb + kc + c * 8;
            cp16(dbase + 20480 + pl * 20480 + row * STR + c * 16, src);
        }
    };

    float acc[4][8][4];
#pragma unroll
    for (int mt = 0; mt < 4; ++mt)
#pragma unroll
        for (int nt = 0; nt < 8; ++nt)
#pragma unroll
            for (int i = 0; i < 4; ++i) acc[mt][nt][i] = 0.0f;

    load_stage(0, 0); CP_COMMIT();
    load_stage(1, 1); CP_COMMIT();

#pragma unroll 1
    for (int kb = 0; kb < NKB; ++kb) {
        CP_WAIT1();
        __syncthreads();
        const int buf = kb % NSTG;
        const uint32_t sbase = sa + buf * STAGE;

#pragma unroll
        for (int ks = 0; ks < 2; ++ks) {
            const uint32_t ko = ks * 32 + tg * 4;   // byte offset within row

            // ---- B fragments (hi & lo) ----
            uint32_t bh[8][2], bl[8][2];
#pragma unroll
            for (int nt = 0; nt < 8; ++nt) {
                const uint32_t ba = sbase + 20480 + (uint32_t)(wc * 64 + nt * 8 + g) * STR + ko;
                bh[nt][0] = lds32(ba);
                bh[nt][1] = lds32(ba + 16);
                bl[nt][0] = lds32(ba + 20480);
                bl[nt][1] = lds32(ba + 20480 + 16);
            }

#pragma unroll
            for (int mt = 0; mt < 4; ++mt) {
                const uint32_t aa = sbase + (uint32_t)(wr * 64 + mt * 16 + g) * STR + ko;
                uint32_t ah[4], al[4];
                ah[0] = lds32(aa);
                ah[1] = lds32(aa + 8 * STR);
                ah[2] = lds32(aa + 16);
                ah[3] = lds32(aa + 8 * STR + 16);
                al[0] = lds32(aa + 10240);
                al[1] = lds32(aa + 10240 + 8 * STR);
                al[2] = lds32(aa + 10240 + 16);
                al[3] = lds32(aa + 10240 + 8 * STR + 16);

#pragma unroll
                for (int nt = 0; nt < 8; ++nt) mma16(acc[mt][nt], ah, bh[nt]);
#pragma unroll
                for (int nt = 0; nt < 8; ++nt) mma16(acc[mt][nt], ah, bl[nt]);
#pragma unroll
                for (int nt = 0; nt < 8; ++nt) mma16(acc[mt][nt], al, bh[nt]);
            }
        }

        if (kb + 2 < NKB) load_stage((kb + 2) % NSTG, kb + 2);
        CP_COMMIT();
    }

    // ---- epilogue ----
    const int rbase = blockIdx.y * 128 + wr * 64 + g;
    const int cbase = blockIdx.x * 256 + wc * 64 + tg * 2;
#pragma unroll
    for (int mt = 0; mt < 4; ++mt) {
#pragma unroll
        for (int nt = 0; nt < 8; ++nt) {
            const int r = rbase + mt * 16;
            const int c = cbase + nt * 8;
            if (EPI == 0) {
                *reinterpret_cast<float2*>(&C[(size_t)r * ldc + c]) =
                    make_float2(acc[mt][nt][0], acc[mt][nt][1]);
                *reinterpret_cast<float2*>(&C[(size_t)(r + 8) * ldc + c]) =
                    make_float2(acc[mt][nt][2], acc[mt][nt][3]);
            } else {
                uint32_t h, l;
                pack2(acc[mt][nt][0], acc[mt][nt][1], h, l);
                *reinterpret_cast<uint32_t*>(Ch + (size_t)r * ldc + c) = h;
                *reinterpret_cast<uint32_t*>(Cl + (size_t)r * ldc + c) = l;
                pack2(acc[mt][nt][2], acc[mt][nt][3], h, l);
                *reinterpret_cast<uint32_t*>(Ch + (size_t)(r + 8) * ldc + c) = h;
                *reinterpret_cast<uint32_t*>(Cl + (size_t)(r + 8) * ldc + c) = l;
            }
        }
    }
}

// ===========================================================================
// GEMM wrappers
// ===========================================================================
__global__ void __launch_bounds__(256, 1)
proj_mm()
{
    const int z = blockIdx.z;                 // 0:Q 1:K 2:V
    const __nv_bfloat16* Bh = g_WTh + (size_t)z * 4096 * 512;
    const __nv_bfloat16* Bl = g_WTl + (size_t)z * 4096 * 512;
    if (z == 0) {
        gemm_nt_bf16<1>(g_xh, g_xl, 512, Bh, Bl, 512, nullptr, g_Qh, g_Ql, 4096);
    } else if (z == 1) {
        gemm_nt_bf16<1>(g_xh, g_xl, 512, Bh, Bl, 512, nullptr, g_Kh, g_Kl, 4096);
    } else {
        gemm_nt_bf16<0>(g_xh, g_xl, 512, Bh, Bl, 512, g_V, nullptr, nullptr, 4096);
    }
}

__global__ void __launch_bounds__(256, 1)
qk_mm()
{
    const int z = blockIdx.z;                 // h*16 + b
    const int h = z >> 4, b = z & 15;
    const size_t off = (size_t)b * 512 * 4096 + h * 512;
    gemm_nt_bf16<0>(g_Qh + off, g_Ql + off, 4096,
                    g_Kh + off, g_Kl + off, 4096,
                    g_P + (size_t)z * 512 * 512, nullptr, nullptr, 512);
}

__global__ void __launch_bounds__(256, 1)
pv_mm(float* __restrict__ out)
{
    const int z = blockIdx.z;
    const int h = z >> 4, b = z & 15;
    const size_t zo = (size_t)z * 512 * 512;
    gemm_nt_bf16<0>(g_Ph + zo, g_Pl + zo, 512,
                    g_VTh + zo, g_VTl + zo, 512,
                    out + (size_t)b * 512 * 4096 + h * 512, nullptr, nullptr, 4096);
}

// ===========================================================================
// Splits / transposes
// ===========================================================================
__global__ void split_x(const float* __restrict__ x)
{
    const size_t i = ((size_t)blockIdx.x * 256 + threadIdx.x) * 4;  // 4.19M elems
    const float4 v = *reinterpret_cast<const float4*>(x + i);
    uint32_t h0, l0, h1, l1;
    pack2(v.x, v.y, h0, l0);
    pack2(v.z, v.w, h1, l1);
    *reinterpret_cast<uint2*>(g_xh + i) = make_uint2(h0, h1);
    *reinterpret_cast<uint2*>(g_xl + i) = make_uint2(l0, l1);
}

__global__ void wt_kernel(const float* __restrict__ wq,
                          const float* __restrict__ wk,
                          const float* __restrict__ wv)
{
    __shared__ float t[32][33];
    const int z = blockIdx.z;
    const float* W = (z == 0) ? wq : (z == 1) ? wk : wv;   // [512, 4096]
    __nv_bfloat16* WTh = g_WTh + (size_t)z * 4096 * 512;
    __nv_bfloat16* WTl = g_WTl + (size_t)z * 4096 * 512;
    const int n0 = blockIdx.x * 32, k0 = blockIdx.y * 32;
    const int tx = threadIdx.x, ty = threadIdx.y;
#pragma unroll
    for (int i = 0; i < 4; ++i)
        t[ty + i * 8][tx] = W[(size_t)(k0 + ty + i * 8) * 4096 + n0 + tx];
    __syncthreads();
#pragma unroll
    for (int i = 0; i < 4; ++i) {
        const float v = t[tx][ty + i * 8];
        const __nv_bfloat16 hb = __float2bfloat16_rn(v);
        const float lo = v - __bfloat162float(hb);
        const size_t idx = (size_t)(n0 + ty + i * 8) * 512 + k0 + tx;
        WTh[idx] = hb;
        WTl[idx] = __float2bfloat16_rn(lo);
    }
}

__global__ void vt_kernel()
{
    __shared__ float t[32][33];
    const int z = blockIdx.z;                 // h*16 + b
    const int h = z >> 4, b = z & 15;
    const int j0 = blockIdx.x * 32, d0 = blockIdx.y * 32;
    const int tx = threadIdx.x, ty = threadIdx.y;
#pragma unroll
    for (int i = 0; i < 4; ++i)
        t[ty + i * 8][tx] = g_V[(size_t)(b * 512 + j0 + ty + i * 8) * 4096 + h * 512 + d0 + tx];
    __syncthreads();
    __nv_bfloat16* VTh = g_VTh + (size_t)z * 512 * 512;
    __nv_bfloat16* VTl = g_VTl + (size_t)z * 512 * 512;
#pragma unroll
    for (int i = 0; i < 4; ++i) {
        const float v = t[tx][ty + i * 8];
        const __nv_bfloat16 hb = __float2bfloat16_rn(v);
        const float lo = v - __bfloat162float(hb);
        const size_t idx = (size_t)(d0 + ty + i * 8) * 512 + j0 + tx;
        VTh[idx] = hb;
        VTl[idx] = __float2bfloat16_rn(lo);
    }
}

// ===========================================================================
// Softmax over rows of g_P (512 wide), writes bf16 hi/lo planes.
// ===========================================================================
__global__ void softmax_kernel()
{
    const size_t row = blockIdx.x;
    const float* p = g_P + row * 512;
    const int t = threadIdx.x;  // 0..255

    float2 v = reinterpret_cast<const float2*>(p)[t];
    __shared__ float red[8];

    float m = fmaxf(v.x, v.y);
#pragma unroll
    for (int o = 16; o > 0; o >>= 1) m = fmaxf(m, __shfl_xor_sync(0xFFFFFFFFu, m, o));
    if ((t & 31) == 0) red[t >> 5] = m;
    __syncthreads();
    m = red[0];
#pragma unroll
    for (int i = 1; i < 8; i++) m = fmaxf(m, red[i]);
    __syncthreads();

    const float e0 = __expf(v.x - m);
    const float e1 = __expf(v.y - m);

    float s = e0 + e1;
#pragma unroll
    for (int o = 16; o > 0; o >>= 1) s += __shfl_xor_sync(0xFFFFFFFFu, s, o);
    if ((t & 31) == 0) red[t >> 5] = s;
    __syncthreads();
    s = red[0];
#pragma unroll
    for (int i = 1; i < 8; i++) s += red[i];

    const float inv = 1.0f / s;
    uint32_t h, l;
    pack2(e0 * inv, e1 * inv, h, l);
    reinterpret_cast<uint32_t*>(g_Ph + row * 512)[t] = h;
    reinterpret_cast<uint32_t*>(g_Pl + row * 512)[t] = l;
}

// ===========================================================================
// Launch
// ===========================================================================
extern "C" void kernel_launch(void* const* d_in, const int* in_sizes, int n_in,
                              void* d_out, int out_size)
{
    const float* x  = (const float*)d_in[0];
    const float* wq = (const float*)d_in[1];
    const float* wk = (const float*)d_in[2];
    const float* wv = (const float*)d_in[3];
    float* out = (float*)d_out;

    cudaFuncSetAttribute(proj_mm, cudaFuncAttributeMaxDynamicSharedMemorySize, GEMM_SMEM);
    cudaFuncSetAttribute(qk_mm,   cudaFuncAttributeMaxDynamicSharedMemorySize, GEMM_SMEM);
    cudaFuncSetAttribute(pv_mm,   cudaFuncAttributeMaxDynamicSharedMemorySize, GEMM_SMEM);

    split_x<<<4096, 256>>>(x);                              // x -> hi/lo planes
    wt_kernel<<<dim3(128, 16, 3), dim3(32, 8)>>>(wq, wk, wv);
    proj_mm<<<dim3(16, 64, 3), 256, GEMM_SMEM>>>();         // Q,K planes; V fp32
    vt_kernel<<<dim3(16, 16, 128), dim3(32, 8)>>>();        // V -> VT planes
    qk_mm<<<dim3(2, 4, 128), 256, GEMM_SMEM>>>();           // scores fp32
    softmax_kernel<<<65536, 256>>>();                       // -> P planes
    pv_mm<<<dim3(2, 4, 128), 256, GEMM_SMEM>>>(out);        // out fp32
}